// round 14
// baseline (speedup 1.0000x reference)
#include <cuda_runtime.h>
#include <cuda_fp16.h>
#include <math.h>
#include <stdint.h>

#define TT 512
#define BB 64
#define HH 1024
#define G4 4096
#define NCTA 128

// ---------------- device scratch (static, no runtime alloc) ----------------
static __device__ float g_gx[(size_t)TT * BB * G4];        // fp32: X@Wx^T + bx + bh
// Wh per-CTA A-frag blob: [c128][mt2][kt64][lane32][reg4] fp16
static __device__ uint32_t g_whp[(size_t)NCTA * 16384];
// Wx B-frag: [nt512][kt64][lane32][reg2] fp16
static __device__ uint32_t g_wxfrag[(size_t)512 * 64 * 64];
// X A-frag: [mt2048][kt64][lane32][reg4] fp16
static __device__ uint32_t g_xfrag[(size_t)2048 * 64 * 128];
// h B-frag (double buffered): [buf2][kt64][nt8][lane32][reg2]
static __device__ uint32_t g_hfrag[2][32768];
// hierarchical barrier: per-CTA flags (128B stride) + broadcast epoch
static __device__ int g_flags[NCTA * 32];
static __device__ int g_go;

// ---------------- mma.sync m16n8k16 fp16 (base sm_80+) ----------------
__device__ __forceinline__ void mma16816(float* c, const uint32_t* a, const uint32_t* b) {
    asm volatile(
        "mma.sync.aligned.m16n8k16.row.col.f32.f16.f16.f32 "
        "{%0,%1,%2,%3}, {%4,%5,%6,%7}, {%8,%9}, {%0,%1,%2,%3};"
        : "+f"(c[0]), "+f"(c[1]), "+f"(c[2]), "+f"(c[3])
        : "r"(a[0]), "r"(a[1]), "r"(a[2]), "r"(a[3]), "r"(b[0]), "r"(b[1]));
}

__device__ __forceinline__ void rel_st(int* p, int v) {
    asm volatile("st.release.gpu.global.s32 [%0], %1;" :: "l"(p), "r"(v) : "memory");
}
__device__ __forceinline__ int acq_ld(const int* p) {
    int v;
    asm volatile("ld.acquire.gpu.global.s32 %0, [%1];" : "=r"(v) : "l"(p) : "memory");
    return v;
}

__device__ __forceinline__ float fast_sigmoid(float x) {
    return 1.f / (1.f + __expf(-x));
}
__device__ __forceinline__ float fast_tanh(float x) {
    return 2.f / (1.f + __expf(-2.f * x)) - 1.f;
}

// ---------------------------------------------------------------------------
// Pack kernels (layouts validated R3-R13).
// A (16x16): lane=((r&7)<<2)|((kk>>1)&3), reg=((kk>>3)<<1)|(r>>3), half=kk&1
// B (8x16):  lane=((n&7)<<2)|((kk>>1)&3), reg=kk>>3,               half=kk&1
// ---------------------------------------------------------------------------
__global__ __launch_bounds__(256) void pack_whp(const float* __restrict__ Wh) {
    int idx = blockIdx.x * 256 + threadIdx.x;   // 4096*1024
    int row = idx >> 10, k = idx & 1023;
    int g = row >> 10, u = row & 1023;
    int c = u >> 3, ul = u & 7;
    int rm = g * 8 + ul;                        // row within CTA's 32
    int mt = rm >> 4, r = rm & 15;
    int kt = k >> 4, kk = k & 15;
    int lane = ((r & 7) << 2) | ((kk >> 1) & 3);
    int reg = ((kk >> 3) << 1) | (r >> 3);
    int half = kk & 1;
    size_t base = (size_t)c * 16384 + ((size_t)mt * 64 + kt) * 128 + lane * 4 + reg;
    ((__half*)&g_whp[base])[half] = __float2half_rn(Wh[idx]);
}

__global__ __launch_bounds__(256) void pack_wx(const float* __restrict__ Wx) {
    int idx = blockIdx.x * 256 + threadIdx.x;   // 4096*1024
    int n = idx >> 10, k = idx & 1023;
    int nt = n >> 3, nl = n & 7;
    int kt = k >> 4, kk = k & 15;
    int lane = (nl << 2) | ((kk >> 1) & 3);
    int reg = kk >> 3;
    int half = kk & 1;
    size_t wi = ((size_t)(nt * 64 + kt) * 32 + lane) * 2 + reg;
    ((__half*)&g_wxfrag[wi])[half] = __float2half_rn(Wx[idx]);
}

__global__ __launch_bounds__(256) void pack_x(const float* __restrict__ X) {
    size_t idx = (size_t)blockIdx.x * 256 + threadIdx.x;  // 32768*1024
    int row = (int)(idx >> 10), k = (int)(idx & 1023);
    int mt = row >> 4, r = row & 15;
    int kt = k >> 4, kk = k & 15;
    int lane = ((r & 7) << 2) | ((kk >> 1) & 3);
    int reg = ((kk >> 3) << 1) | (r >> 3);
    int half = kk & 1;
    size_t wi = (((size_t)mt * 64 + kt) * 32 + lane) * 4 + reg;
    ((__half*)&g_xfrag[wi])[half] = __float2half_rn(X[idx]);
}

__global__ __launch_bounds__(256) void pack_h0(const float* __restrict__ h0) {
    int idx = blockIdx.x * 256 + threadIdx.x;   // 64*1024
    int b = idx >> 10, u = idx & 1023;
    int kt = u >> 4, kk = u & 15;
    int nt = b >> 3;
    int lane = ((b & 7) << 2) | ((kk >> 1) & 3);
    int reg = kk >> 3;
    int half = kk & 1;
    size_t wi = ((size_t)(kt * 8 + nt) * 32 + lane) * 2 + reg;
    ((__half*)&g_hfrag[0][wi])[half] = __float2half_rn(h0[idx]);
}

__global__ void reset_bar() {
    int i = threadIdx.x;
    if (i < NCTA) g_flags[i * 32] = 0;
    if (i == 0) g_go = 0;
}

// ---------------------------------------------------------------------------
// gx GEMM (R6 verbatim, at the HMMA floor): gx = X@Wx^T + bx + bh
// ---------------------------------------------------------------------------
__global__ __launch_bounds__(256) void gx_mma_kernel(
    const float* __restrict__ bx, const float* __restrict__ bh)
{
    const int tid = threadIdx.x;
    const int wid = tid >> 5, lane = tid & 31;
    const int wm = wid & 1, wn = wid >> 1;
    const int mtb = blockIdx.y * 8 + wm * 4;
    const int ntb = blockIdx.x * 16 + wn * 4;

    float acc[4][4][4];
#pragma unroll
    for (int i = 0; i < 4; i++)
#pragma unroll
        for (int j = 0; j < 4; j++)
#pragma unroll
            for (int q = 0; q < 4; q++) acc[i][j][q] = 0.f;

    const uint32_t* Af = g_xfrag + (size_t)lane * 4;
    const uint32_t* Bf = g_wxfrag + (size_t)lane * 2;

#pragma unroll 2
    for (int kt = 0; kt < 64; kt++) {
        uint32_t b_f[4][2];
#pragma unroll
        for (int nt = 0; nt < 4; nt++) {
            size_t bo = (size_t)((ntb + nt) * 64 + kt) * 64;
            *(uint2*)b_f[nt] = *(const uint2*)(Bf + bo);
        }
#pragma unroll
        for (int mt = 0; mt < 4; mt++) {
            size_t ao = ((size_t)(mtb + mt) * 64 + kt) * 128;
            uint32_t a[4];
            *(uint4*)a = *(const uint4*)(Af + ao);
#pragma unroll
            for (int nt = 0; nt < 4; nt++)
                mma16816(acc[mt][nt], a, b_f[nt]);
        }
    }

#pragma unroll
    for (int mt = 0; mt < 4; mt++) {
        int row = (mtb + mt) * 16 + (lane >> 2);
#pragma unroll
        for (int nt = 0; nt < 4; nt++) {
            int col = (ntb + nt) * 8 + (lane & 3) * 2;
            float bb0 = bx[col] + bh[col];
            float bb1 = bx[col + 1] + bh[col + 1];
            float2 v0 = make_float2(acc[mt][nt][0] + bb0, acc[mt][nt][1] + bb1);
            float2 v1 = make_float2(acc[mt][nt][2] + bb0, acc[mt][nt][3] + bb1);
            *(float2*)(g_gx + (size_t)row * G4 + col) = v0;
            *(float2*)(g_gx + (size_t)(row + 8) * G4 + col) = v1;
        }
    }
}

// ---------------------------------------------------------------------------
// Persistent recurrence: 128 CTAs x 256 threads, 1 CTA/SM (R13 layout).
// Warp w = (q = w&3, nh = w>>2); Wh A-fragments in registers.
// Barrier (R14): per-CTA release flag -> CTA0 aggregates (128-thread parallel
// poll) -> single broadcast 'go' word -> all CTAs poll go. No atomics.
// ---------------------------------------------------------------------------
#define SO_CS   (34816)                      // Gs 4*32*68*4
#define SM_TOTAL (SO_CS + 2048)              // 36864

__global__ __launch_bounds__(256, 1) void lstm_rec(
    const float* __restrict__ c0,
    float* __restrict__ out,
    float* __restrict__ hfin, float* __restrict__ cfin,
    int full)
{
    extern __shared__ __align__(16) char sm[];
    float (*Gs)[32][68] = (float (*)[32][68])sm;
    float* cs = (float*)(sm + SO_CS);

    const int cta = blockIdx.x;
    const int tid = threadIdx.x;
    const int w = tid >> 5, lane = tid & 31;
    const int q = w & 3, nh = w >> 2;
    const int r0q = lane >> 2;
    const int c0q = (lane & 3) * 2;

    // ---- init: Wh A-fragments -> registers; cell state -> smem ----
    uint32_t areg[2][16][4];
    {
        const uint32_t* src = g_whp + (size_t)cta * 16384;
        const int ktb = q * 16;
#pragma unroll
        for (int mt = 0; mt < 2; mt++)
#pragma unroll
            for (int kl = 0; kl < 16; kl++) {
                *(uint4*)areg[mt][kl] =
                    *(const uint4*)(src + ((size_t)mt * 64 + ktb + kl) * 128 + lane * 4);
            }
        for (int i = tid; i < 512; i += 256) {
            int b = i >> 3, ul = i & 7;
            cs[i] = c0[(size_t)b * HH + cta * 8 + ul];
        }
    }
    __syncthreads();

    const int kt0 = q * 16;
    for (int t = 0; t < TT; t++) {
        // ---- prefetch gate pre-activations (hidden under GEMM) ----
        float gpre[2][4];
#pragma unroll
        for (int pp = 0; pp < 2; pp++) {
            const int p = tid + pp * 256;
            const int b = p >> 3, ul = p & 7;
            const float* gxr = g_gx + ((size_t)t * BB + b) * G4 + cta * 8 + ul;
#pragma unroll
            for (int g = 0; g < 4; g++) gpre[pp][g] = __ldcg(gxr + g * HH);
        }

        // ---- rec GEMM: (q, nh) warp tile, A in registers ----
        float acc[2][4][4];
#pragma unroll
        for (int i = 0; i < 2; i++)
#pragma unroll
            for (int j = 0; j < 4; j++)
#pragma unroll
                for (int r = 0; r < 4; r++) acc[i][j][r] = 0.f;

        const uint32_t* Bf = &g_hfrag[t & 1][0];
#pragma unroll
        for (int kl = 0; kl < 16; kl++) {
            const int kt = kt0 + kl;
            uint2 bf[4];
#pragma unroll
            for (int ntl = 0; ntl < 4; ntl++) {
                uint32_t off = (uint32_t)(kt * 8 + nh * 4 + ntl) * 64 + lane * 2;
                bf[ntl] = __ldcg((const uint2*)(Bf + off));
            }
#pragma unroll
            for (int ntl = 0; ntl < 4; ntl++) {
                mma16816(acc[0][ntl], areg[0][kl], (const uint32_t*)&bf[ntl]);
                mma16816(acc[1][ntl], areg[1][kl], (const uint32_t*)&bf[ntl]);
            }
        }

        // ---- scatter partials: Gs[q][row32][b] ----
#pragma unroll
        for (int mt = 0; mt < 2; mt++) {
            const int rbase = mt * 16 + r0q;
#pragma unroll
            for (int ntl = 0; ntl < 4; ntl++) {
                int col = (nh * 4 + ntl) * 8 + c0q;
                Gs[q][rbase][col]     = acc[mt][ntl][0];
                Gs[q][rbase][col + 1] = acc[mt][ntl][1];
                Gs[q][rbase + 8][col]     = acc[mt][ntl][2];
                Gs[q][rbase + 8][col + 1] = acc[mt][ntl][3];
            }
        }
        __syncthreads();

        // ---- cell update: 2 cells per thread ----
        float* outt = out + (size_t)t * BB * HH;
        const int nb = (t + 1) & 1;
        float hsave[2], csave[2];
#pragma unroll
        for (int pp = 0; pp < 2; pp++) {
            const int p = tid + pp * 256;
            const int b = p >> 3, ul = p & 7;
            const int u = cta * 8 + ul;

            float x0 = Gs[0][ul][b] + Gs[1][ul][b] + Gs[2][ul][b] + Gs[3][ul][b] + gpre[pp][0];
            float x1 = Gs[0][8 + ul][b] + Gs[1][8 + ul][b] + Gs[2][8 + ul][b] + Gs[3][8 + ul][b] + gpre[pp][1];
            float x2 = Gs[0][16 + ul][b] + Gs[1][16 + ul][b] + Gs[2][16 + ul][b] + Gs[3][16 + ul][b] + gpre[pp][2];
            float x3 = Gs[0][24 + ul][b] + Gs[1][24 + ul][b] + Gs[2][24 + ul][b] + Gs[3][24 + ul][b] + gpre[pp][3];

            float ig = fast_sigmoid(x0);
            float fg = fast_sigmoid(x1);
            float og = fast_sigmoid(x2);
            float ng = fast_tanh(x3);

            float cprev = cs[p];
            float cnew = fg * cprev + ig * ng;
            float hnew = og * fast_tanh(cnew);
            cs[p] = cnew;
            hsave[pp] = hnew;
            csave[pp] = cnew;

            // publish next-step B fragment (fp16)
            int kt = u >> 4, kk = u & 15, nt = b >> 3;
            int lt = ((b & 7) << 2) | ((kk >> 1) & 3);
            int rg = kk >> 3, hf = kk & 1;
            size_t wi = ((size_t)(kt * 8 + nt) * 32 + lt) * 2 + rg;
            ((__half*)&g_hfrag[nb][wi])[hf] = __float2half_rn(hnew);

            if (t == TT - 1 && full) {
                hfin[(size_t)b * HH + u] = hnew;
                cfin[(size_t)b * HH + u] = cnew;
            }
        }

        // ---- hierarchical grid barrier ----
        __syncthreads();                          // h publishes done CTA-wide
        if (tid == 0) rel_st(&g_flags[cta * 32], t + 1);

        // shadow: output stores (not consumed this pass)
#pragma unroll
        for (int pp = 0; pp < 2; pp++) {
            const int p = tid + pp * 256;
            const int b = p >> 3, ul = p & 7;
            outt[(size_t)b * HH + cta * 8 + ul] = hsave[pp];
        }

        if (cta == 0) {
            // aggregate: 128 parallel flag loads, then broadcast go
            int ready;
            do {
                int ok = 1;
                if (tid < NCTA) ok = (acq_ld(&g_flags[tid * 32]) >= t + 1);
                ready = __syncthreads_and(ok);
            } while (!ready);
            if (tid == 0) rel_st(&g_go, t + 1);
        } else {
            if (tid == 0) {
                while (acq_ld(&g_go) < t + 1) __nanosleep(32);
            }
            __syncthreads();
        }
    }
}

// ---------------------------------------------------------------------------
extern "C" void kernel_launch(void* const* d_in, const int* in_sizes, int n_in,
                              void* d_out, int out_size)
{
    const float* input_ = (const float*)d_in[0];
    const float* h0     = (const float*)d_in[1];
    const float* c0     = (const float*)d_in[2];
    const float* Wx     = (const float*)d_in[3];
    const float* Wh     = (const float*)d_in[4];
    const float* bx     = (const float*)d_in[5];
    const float* bh     = (const float*)d_in[6];
    float* out = (float*)d_out;
    (void)in_sizes; (void)n_in;

    cudaFuncSetAttribute(lstm_rec, cudaFuncAttributeMaxDynamicSharedMemorySize, SM_TOTAL);

    reset_bar<<<1, 128>>>();
    pack_whp<<<(G4 * HH) / 256, 256>>>(Wh);
    pack_wx<<<(G4 * HH) / 256, 256>>>(Wx);
    pack_x<<<(int)(((size_t)TT * BB * HH) / 256), 256>>>(input_);
    pack_h0<<<(BB * HH) / 256, 256>>>(h0);

    dim3 ggrid(G4 / 128, (TT * BB) / 128);
    gx_mma_kernel<<<ggrid, 256>>>(bx, bh);

    long long need = (long long)TT * BB * HH + 2LL * BB * HH;
    int full = (out_size >= need) ? 1 : 0;
    float* hfin = out + (size_t)TT * BB * HH;
    float* cfin = hfin + (size_t)BB * HH;

    lstm_rec<<<NCTA, 256, SM_TOTAL>>>(c0, out, hfin, cfin, full);
}

// round 15
// speedup vs baseline: 1.1855x; 1.1855x over previous
#include <cuda_runtime.h>
#include <cuda_fp16.h>
#include <math.h>
#include <stdint.h>

#define TT 512
#define BB 64
#define HH 1024
#define G4 4096
#define NCTA 128

// ---------------- device scratch (static, no runtime alloc) ----------------
static __device__ float g_gx[(size_t)TT * BB * G4];        // fp32: X@Wx^T + bx + bh
// Wh per-CTA A-frag blob: [c128][mt2][kt64][lane32][reg4] fp16
static __device__ uint32_t g_whp[(size_t)NCTA * 16384];
// Wx B-frag: [nt512][kt64][lane32][reg2] fp16
static __device__ uint32_t g_wxfrag[(size_t)512 * 64 * 64];
// X A-frag: [mt2048][kt64][lane32][reg4] fp16
static __device__ uint32_t g_xfrag[(size_t)2048 * 64 * 128];
// h B-frag (double buffered): [buf2][kt64][nt8][lane32][reg2]
static __device__ uint32_t g_hfrag[2][32768];
static __device__ int g_arrive;

// ---------------- mma.sync m16n8k16 fp16 (base sm_80+) ----------------
__device__ __forceinline__ void mma16816(float* c, const uint32_t* a, const uint32_t* b) {
    asm volatile(
        "mma.sync.aligned.m16n8k16.row.col.f32.f16.f16.f32 "
        "{%0,%1,%2,%3}, {%4,%5,%6,%7}, {%8,%9}, {%0,%1,%2,%3};"
        : "+f"(c[0]), "+f"(c[1]), "+f"(c[2]), "+f"(c[3])
        : "r"(a[0]), "r"(a[1]), "r"(a[2]), "r"(a[3]), "r"(b[0]), "r"(b[1]));
}

__device__ __forceinline__ void bar_release_add(int* p) {
    asm volatile("red.release.gpu.global.add.s32 [%0], 1;" :: "l"(p) : "memory");
}
__device__ __forceinline__ int bar_acquire_ld(const int* p) {
    int v;
    asm volatile("ld.acquire.gpu.global.s32 %0, [%1];" : "=r"(v) : "l"(p) : "memory");
    return v;
}

__device__ __forceinline__ float fast_sigmoid(float x) {
    return 1.f / (1.f + __expf(-x));
}
__device__ __forceinline__ float fast_tanh(float x) {
    return 2.f / (1.f + __expf(-2.f * x)) - 1.f;
}

// ---------------------------------------------------------------------------
// Pack kernels (layouts validated R3-R14).
// A (16x16): lane=((r&7)<<2)|((kk>>1)&3), reg=((kk>>3)<<1)|(r>>3), half=kk&1
// B (8x16):  lane=((n&7)<<2)|((kk>>1)&3), reg=kk>>3,               half=kk&1
// ---------------------------------------------------------------------------
__global__ __launch_bounds__(256) void pack_whp(const float* __restrict__ Wh) {
    int idx = blockIdx.x * 256 + threadIdx.x;   // 4096*1024
    int row = idx >> 10, k = idx & 1023;
    int g = row >> 10, u = row & 1023;
    int c = u >> 3, ul = u & 7;
    int rm = g * 8 + ul;                        // row within CTA's 32
    int mt = rm >> 4, r = rm & 15;
    int kt = k >> 4, kk = k & 15;
    int lane = ((r & 7) << 2) | ((kk >> 1) & 3);
    int reg = ((kk >> 3) << 1) | (r >> 3);
    int half = kk & 1;
    size_t base = (size_t)c * 16384 + ((size_t)mt * 64 + kt) * 128 + lane * 4 + reg;
    ((__half*)&g_whp[base])[half] = __float2half_rn(Wh[idx]);
}

__global__ __launch_bounds__(256) void pack_wx(const float* __restrict__ Wx) {
    int idx = blockIdx.x * 256 + threadIdx.x;   // 4096*1024
    int n = idx >> 10, k = idx & 1023;
    int nt = n >> 3, nl = n & 7;
    int kt = k >> 4, kk = k & 15;
    int lane = (nl << 2) | ((kk >> 1) & 3);
    int reg = kk >> 3;
    int half = kk & 1;
    size_t wi = ((size_t)(nt * 64 + kt) * 32 + lane) * 2 + reg;
    ((__half*)&g_wxfrag[wi])[half] = __float2half_rn(Wx[idx]);
}

__global__ __launch_bounds__(256) void pack_x(const float* __restrict__ X) {
    size_t idx = (size_t)blockIdx.x * 256 + threadIdx.x;  // 32768*1024
    int row = (int)(idx >> 10), k = (int)(idx & 1023);
    int mt = row >> 4, r = row & 15;
    int kt = k >> 4, kk = k & 15;
    int lane = ((r & 7) << 2) | ((kk >> 1) & 3);
    int reg = ((kk >> 3) << 1) | (r >> 3);
    int half = kk & 1;
    size_t wi = (((size_t)mt * 64 + kt) * 32 + lane) * 4 + reg;
    ((__half*)&g_xfrag[wi])[half] = __float2half_rn(X[idx]);
}

__global__ __launch_bounds__(256) void pack_h0(const float* __restrict__ h0) {
    int idx = blockIdx.x * 256 + threadIdx.x;   // 64*1024
    int b = idx >> 10, u = idx & 1023;
    int kt = u >> 4, kk = u & 15;
    int nt = b >> 3;
    int lane = ((b & 7) << 2) | ((kk >> 1) & 3);
    int reg = kk >> 3;
    int half = kk & 1;
    size_t wi = ((size_t)(kt * 8 + nt) * 32 + lane) * 2 + reg;
    ((__half*)&g_hfrag[0][wi])[half] = __float2half_rn(h0[idx]);
}

__global__ void reset_bar() { g_arrive = 0; }

// ---------------------------------------------------------------------------
// gx GEMM (R6 verbatim, at the HMMA floor): gx = X@Wx^T + bx + bh
// ---------------------------------------------------------------------------
__global__ __launch_bounds__(256) void gx_mma_kernel(
    const float* __restrict__ bx, const float* __restrict__ bh)
{
    const int tid = threadIdx.x;
    const int wid = tid >> 5, lane = tid & 31;
    const int wm = wid & 1, wn = wid >> 1;
    const int mtb = blockIdx.y * 8 + wm * 4;
    const int ntb = blockIdx.x * 16 + wn * 4;

    float acc[4][4][4];
#pragma unroll
    for (int i = 0; i < 4; i++)
#pragma unroll
        for (int j = 0; j < 4; j++)
#pragma unroll
            for (int q = 0; q < 4; q++) acc[i][j][q] = 0.f;

    const uint32_t* Af = g_xfrag + (size_t)lane * 4;
    const uint32_t* Bf = g_wxfrag + (size_t)lane * 2;

#pragma unroll 2
    for (int kt = 0; kt < 64; kt++) {
        uint32_t b_f[4][2];
#pragma unroll
        for (int nt = 0; nt < 4; nt++) {
            size_t bo = (size_t)((ntb + nt) * 64 + kt) * 64;
            *(uint2*)b_f[nt] = *(const uint2*)(Bf + bo);
        }
#pragma unroll
        for (int mt = 0; mt < 4; mt++) {
            size_t ao = ((size_t)(mtb + mt) * 64 + kt) * 128;
            uint32_t a[4];
            *(uint4*)a = *(const uint4*)(Af + ao);
#pragma unroll
            for (int nt = 0; nt < 4; nt++)
                mma16816(acc[mt][nt], a, b_f[nt]);
        }
    }

#pragma unroll
    for (int mt = 0; mt < 4; mt++) {
        int row = (mtb + mt) * 16 + (lane >> 2);
#pragma unroll
        for (int nt = 0; nt < 4; nt++) {
            int col = (ntb + nt) * 8 + (lane & 3) * 2;
            float bb0 = bx[col] + bh[col];
            float bb1 = bx[col + 1] + bh[col + 1];
            float2 v0 = make_float2(acc[mt][nt][0] + bb0, acc[mt][nt][1] + bb1);
            float2 v1 = make_float2(acc[mt][nt][2] + bb0, acc[mt][nt][3] + bb1);
            *(float2*)(g_gx + (size_t)row * G4 + col) = v0;
            *(float2*)(g_gx + (size_t)(row + 8) * G4 + col) = v1;
        }
    }
}

// ---------------------------------------------------------------------------
// Persistent recurrence: 128 CTAs x 256 threads, 1 CTA/SM (R13 layout).
// Warp w = (q = w&3, nh = w>>2); Wh A-fragments in registers (loaded once).
// Barrier: R13's single release-counter + tid0 acquire poll (proven best).
// Epilogue: MUFU-based sigmoid/tanh (R14's one good half).
// ---------------------------------------------------------------------------
#define SO_CS   (34816)                      // Gs 4*32*68*4
#define SM_TOTAL (SO_CS + 2048)              // 36864

__global__ __launch_bounds__(256, 1) void lstm_rec(
    const float* __restrict__ c0,
    float* __restrict__ out,
    float* __restrict__ hfin, float* __restrict__ cfin,
    int full)
{
    extern __shared__ __align__(16) char sm[];
    float (*Gs)[32][68] = (float (*)[32][68])sm;
    float* cs = (float*)(sm + SO_CS);

    const int cta = blockIdx.x;
    const int tid = threadIdx.x;
    const int w = tid >> 5, lane = tid & 31;
    const int q = w & 3, nh = w >> 2;
    const int r0q = lane >> 2;
    const int c0q = (lane & 3) * 2;

    // ---- init: Wh A-fragments -> registers (once); cell state -> smem ----
    uint32_t areg[2][16][4];
    {
        const uint32_t* src = g_whp + (size_t)cta * 16384;
        const int ktb = q * 16;
#pragma unroll
        for (int mt = 0; mt < 2; mt++)
#pragma unroll
            for (int kl = 0; kl < 16; kl++) {
                *(uint4*)areg[mt][kl] =
                    *(const uint4*)(src + ((size_t)mt * 64 + ktb + kl) * 128 + lane * 4);
            }
        for (int i = tid; i < 512; i += 256) {
            int b = i >> 3, ul = i & 7;
            cs[i] = c0[(size_t)b * HH + cta * 8 + ul];
        }
    }
    __syncthreads();

    const int kt0 = q * 16;
    for (int t = 0; t < TT; t++) {
        // ---- prefetch gate pre-activations (hidden under GEMM) ----
        float gpre[2][4];
#pragma unroll
        for (int pp = 0; pp < 2; pp++) {
            const int p = tid + pp * 256;
            const int b = p >> 3, ul = p & 7;
            const float* gxr = g_gx + ((size_t)t * BB + b) * G4 + cta * 8 + ul;
#pragma unroll
            for (int g = 0; g < 4; g++) gpre[pp][g] = __ldcg(gxr + g * HH);
        }

        // ---- rec GEMM: (q, nh) warp tile, A in registers ----
        float acc[2][4][4];
#pragma unroll
        for (int i = 0; i < 2; i++)
#pragma unroll
            for (int j = 0; j < 4; j++)
#pragma unroll
                for (int r = 0; r < 4; r++) acc[i][j][r] = 0.f;

        const uint32_t* Bf = &g_hfrag[t & 1][0];
#pragma unroll
        for (int kl = 0; kl < 16; kl++) {
            const int kt = kt0 + kl;
            uint2 bf[4];
#pragma unroll
            for (int ntl = 0; ntl < 4; ntl++) {
                uint32_t off = (uint32_t)(kt * 8 + nh * 4 + ntl) * 64 + lane * 2;
                bf[ntl] = __ldcg((const uint2*)(Bf + off));
            }
#pragma unroll
            for (int ntl = 0; ntl < 4; ntl++) {
                mma16816(acc[0][ntl], areg[0][kl], (const uint32_t*)&bf[ntl]);
                mma16816(acc[1][ntl], areg[1][kl], (const uint32_t*)&bf[ntl]);
            }
        }

        // ---- scatter partials: Gs[q][row32][b] ----
#pragma unroll
        for (int mt = 0; mt < 2; mt++) {
            const int rbase = mt * 16 + r0q;
#pragma unroll
            for (int ntl = 0; ntl < 4; ntl++) {
                int col = (nh * 4 + ntl) * 8 + c0q;
                Gs[q][rbase][col]     = acc[mt][ntl][0];
                Gs[q][rbase][col + 1] = acc[mt][ntl][1];
                Gs[q][rbase + 8][col]     = acc[mt][ntl][2];
                Gs[q][rbase + 8][col + 1] = acc[mt][ntl][3];
            }
        }
        __syncthreads();

        // ---- cell update: 2 cells per thread ----
        float* outt = out + (size_t)t * BB * HH;
        const int nb = (t + 1) & 1;
        float hsave[2], csave[2];
#pragma unroll
        for (int pp = 0; pp < 2; pp++) {
            const int p = tid + pp * 256;
            const int b = p >> 3, ul = p & 7;
            const int u = cta * 8 + ul;

            float x0 = Gs[0][ul][b] + Gs[1][ul][b] + Gs[2][ul][b] + Gs[3][ul][b] + gpre[pp][0];
            float x1 = Gs[0][8 + ul][b] + Gs[1][8 + ul][b] + Gs[2][8 + ul][b] + Gs[3][8 + ul][b] + gpre[pp][1];
            float x2 = Gs[0][16 + ul][b] + Gs[1][16 + ul][b] + Gs[2][16 + ul][b] + Gs[3][16 + ul][b] + gpre[pp][2];
            float x3 = Gs[0][24 + ul][b] + Gs[1][24 + ul][b] + Gs[2][24 + ul][b] + Gs[3][24 + ul][b] + gpre[pp][3];

            float ig = fast_sigmoid(x0);
            float fg = fast_sigmoid(x1);
            float og = fast_sigmoid(x2);
            float ng = fast_tanh(x3);

            float cprev = cs[p];
            float cnew = fg * cprev + ig * ng;
            float hnew = og * fast_tanh(cnew);
            cs[p] = cnew;
            hsave[pp] = hnew;
            csave[pp] = cnew;

            // publish next-step B fragment (fp16)
            int kt = u >> 4, kk = u & 15, nt = b >> 3;
            int lt = ((b & 7) << 2) | ((kk >> 1) & 3);
            int rg = kk >> 3, hf = kk & 1;
            size_t wi = ((size_t)(kt * 8 + nt) * 32 + lt) * 2 + rg;
            ((__half*)&g_hfrag[nb][wi])[hf] = __float2half_rn(hnew);

            if (t == TT - 1 && full) {
                hfin[(size_t)b * HH + u] = hnew;
                cfin[(size_t)b * HH + u] = cnew;
            }
        }

        // ---- grid barrier (R13: single release counter, tid0 poll) ----
        __syncthreads();
        if (tid == 0) bar_release_add(&g_arrive);

        // shadow: output stores (not consumed this pass)
#pragma unroll
        for (int pp = 0; pp < 2; pp++) {
            const int p = tid + pp * 256;
            const int b = p >> 3, ul = p & 7;
            outt[(size_t)b * HH + cta * 8 + ul] = hsave[pp];
        }

        if (tid == 0) {
            const int target = NCTA * (t + 1);
            while (bar_acquire_ld(&g_arrive) < target) __nanosleep(32);
        }
        __syncthreads();
    }
}

// ---------------------------------------------------------------------------
extern "C" void kernel_launch(void* const* d_in, const int* in_sizes, int n_in,
                              void* d_out, int out_size)
{
    const float* input_ = (const float*)d_in[0];
    const float* h0     = (const float*)d_in[1];
    const float* c0     = (const float*)d_in[2];
    const float* Wx     = (const float*)d_in[3];
    const float* Wh     = (const float*)d_in[4];
    const float* bx     = (const float*)d_in[5];
    const float* bh     = (const float*)d_in[6];
    float* out = (float*)d_out;
    (void)in_sizes; (void)n_in;

    cudaFuncSetAttribute(lstm_rec, cudaFuncAttributeMaxDynamicSharedMemorySize, SM_TOTAL);

    reset_bar<<<1, 1>>>();
    pack_whp<<<(G4 * HH) / 256, 256>>>(Wh);
    pack_wx<<<(G4 * HH) / 256, 256>>>(Wx);
    pack_x<<<(int)(((size_t)TT * BB * HH) / 256), 256>>>(input_);
    pack_h0<<<(BB * HH) / 256, 256>>>(h0);

    dim3 ggrid(G4 / 128, (TT * BB) / 128);
    gx_mma_kernel<<<ggrid, 256>>>(bx, bh);

    long long need = (long long)TT * BB * HH + 2LL * BB * HH;
    int full = (out_size >= need) ? 1 : 0;
    float* hfin = out + (size_t)TT * BB * HH;
    float* cfin = hfin + (size_t)BB * HH;

    lstm_rec<<<NCTA, 256, SM_TOTAL>>>(c0, out, hfin, cfin, full);
}

// round 16
// speedup vs baseline: 1.2009x; 1.0129x over previous
#include <cuda_runtime.h>
#include <cuda_fp16.h>
#include <math.h>
#include <stdint.h>

#define TT 512
#define BB 64
#define HH 1024
#define G4 4096
#define NCTA 128

// ---------------- device scratch (static, no runtime alloc) ----------------
static __device__ float g_gx[(size_t)TT * BB * G4];        // fp32: X@Wx^T + bx + bh
// Wh per-CTA A-frag blob: [c128][mt2][kt64][lane32][reg4] fp16
static __device__ uint32_t g_whp[(size_t)NCTA * 16384];
// Wx B-frag: [nt512][kt64][lane32][reg2] fp16
static __device__ uint32_t g_wxfrag[(size_t)512 * 64 * 64];
// X A-frag: [mt2048][kt64][lane32][reg4] fp16
static __device__ uint32_t g_xfrag[(size_t)2048 * 64 * 128];
// h B-frag (double buffered): [buf2][kt64][nt8][lane32][reg2]
static __device__ uint32_t g_hfrag[2][32768];
// 4 quarter barrier counters, 128B padded (CTAs [32q,32q+32) arrive at q)
static __device__ int g_arrive4[4 * 32];

// ---------------- mma.sync m16n8k16 fp16 (base sm_80+) ----------------
__device__ __forceinline__ void mma16816(float* c, const uint32_t* a, const uint32_t* b) {
    asm volatile(
        "mma.sync.aligned.m16n8k16.row.col.f32.f16.f16.f32 "
        "{%0,%1,%2,%3}, {%4,%5,%6,%7}, {%8,%9}, {%0,%1,%2,%3};"
        : "+f"(c[0]), "+f"(c[1]), "+f"(c[2]), "+f"(c[3])
        : "r"(a[0]), "r"(a[1]), "r"(a[2]), "r"(a[3]), "r"(b[0]), "r"(b[1]));
}

__device__ __forceinline__ void bar_release_add(int* p) {
    asm volatile("red.release.gpu.global.add.s32 [%0], 1;" :: "l"(p) : "memory");
}
__device__ __forceinline__ int bar_acquire_ld(const int* p) {
    int v;
    asm volatile("ld.acquire.gpu.global.s32 %0, [%1];" : "=r"(v) : "l"(p) : "memory");
    return v;
}

__device__ __forceinline__ float fast_sigmoid(float x) {
    return 1.f / (1.f + __expf(-x));
}
__device__ __forceinline__ float fast_tanh(float x) {
    return 2.f / (1.f + __expf(-2.f * x)) - 1.f;
}

// ---------------------------------------------------------------------------
// Pack kernels (layouts validated R3-R15).
// A (16x16): lane=((r&7)<<2)|((kk>>1)&3), reg=((kk>>3)<<1)|(r>>3), half=kk&1
// B (8x16):  lane=((n&7)<<2)|((kk>>1)&3), reg=kk>>3,               half=kk&1
// ---------------------------------------------------------------------------
__global__ __launch_bounds__(256) void pack_whp(const float* __restrict__ Wh) {
    int idx = blockIdx.x * 256 + threadIdx.x;   // 4096*1024
    int row = idx >> 10, k = idx & 1023;
    int g = row >> 10, u = row & 1023;
    int c = u >> 3, ul = u & 7;
    int rm = g * 8 + ul;                        // row within CTA's 32
    int mt = rm >> 4, r = rm & 15;
    int kt = k >> 4, kk = k & 15;
    int lane = ((r & 7) << 2) | ((kk >> 1) & 3);
    int reg = ((kk >> 3) << 1) | (r >> 3);
    int half = kk & 1;
    size_t base = (size_t)c * 16384 + ((size_t)mt * 64 + kt) * 128 + lane * 4 + reg;
    ((__half*)&g_whp[base])[half] = __float2half_rn(Wh[idx]);
}

__global__ __launch_bounds__(256) void pack_wx(const float* __restrict__ Wx) {
    int idx = blockIdx.x * 256 + threadIdx.x;   // 4096*1024
    int n = idx >> 10, k = idx & 1023;
    int nt = n >> 3, nl = n & 7;
    int kt = k >> 4, kk = k & 15;
    int lane = (nl << 2) | ((kk >> 1) & 3);
    int reg = kk >> 3;
    int half = kk & 1;
    size_t wi = ((size_t)(nt * 64 + kt) * 32 + lane) * 2 + reg;
    ((__half*)&g_wxfrag[wi])[half] = __float2half_rn(Wx[idx]);
}

__global__ __launch_bounds__(256) void pack_x(const float* __restrict__ X) {
    size_t idx = (size_t)blockIdx.x * 256 + threadIdx.x;  // 32768*1024
    int row = (int)(idx >> 10), k = (int)(idx & 1023);
    int mt = row >> 4, r = row & 15;
    int kt = k >> 4, kk = k & 15;
    int lane = ((r & 7) << 2) | ((kk >> 1) & 3);
    int reg = ((kk >> 3) << 1) | (r >> 3);
    int half = kk & 1;
    size_t wi = (((size_t)mt * 64 + kt) * 32 + lane) * 4 + reg;
    ((__half*)&g_xfrag[wi])[half] = __float2half_rn(X[idx]);
}

__global__ __launch_bounds__(256) void pack_h0(const float* __restrict__ h0) {
    int idx = blockIdx.x * 256 + threadIdx.x;   // 64*1024
    int b = idx >> 10, u = idx & 1023;
    int kt = u >> 4, kk = u & 15;
    int nt = b >> 3;
    int lane = ((b & 7) << 2) | ((kk >> 1) & 3);
    int reg = kk >> 3;
    int half = kk & 1;
    size_t wi = ((size_t)(kt * 8 + nt) * 32 + lane) * 2 + reg;
    ((__half*)&g_hfrag[0][wi])[half] = __float2half_rn(h0[idx]);
}

__global__ void reset_bar() {
    int i = threadIdx.x;
    if (i < 4) g_arrive4[i * 32] = 0;
}

// ---------------------------------------------------------------------------
// gx GEMM (R6 verbatim, at the HMMA floor): gx = X@Wx^T + bx + bh
// ---------------------------------------------------------------------------
__global__ __launch_bounds__(256) void gx_mma_kernel(
    const float* __restrict__ bx, const float* __restrict__ bh)
{
    const int tid = threadIdx.x;
    const int wid = tid >> 5, lane = tid & 31;
    const int wm = wid & 1, wn = wid >> 1;
    const int mtb = blockIdx.y * 8 + wm * 4;
    const int ntb = blockIdx.x * 16 + wn * 4;

    float acc[4][4][4];
#pragma unroll
    for (int i = 0; i < 4; i++)
#pragma unroll
        for (int j = 0; j < 4; j++)
#pragma unroll
            for (int q = 0; q < 4; q++) acc[i][j][q] = 0.f;

    const uint32_t* Af = g_xfrag + (size_t)lane * 4;
    const uint32_t* Bf = g_wxfrag + (size_t)lane * 2;

#pragma unroll 2
    for (int kt = 0; kt < 64; kt++) {
        uint32_t b_f[4][2];
#pragma unroll
        for (int nt = 0; nt < 4; nt++) {
            size_t bo = (size_t)((ntb + nt) * 64 + kt) * 64;
            *(uint2*)b_f[nt] = *(const uint2*)(Bf + bo);
        }
#pragma unroll
        for (int mt = 0; mt < 4; mt++) {
            size_t ao = ((size_t)(mtb + mt) * 64 + kt) * 128;
            uint32_t a[4];
            *(uint4*)a = *(const uint4*)(Af + ao);
#pragma unroll
            for (int nt = 0; nt < 4; nt++)
                mma16816(acc[mt][nt], a, b_f[nt]);
        }
    }

#pragma unroll
    for (int mt = 0; mt < 4; mt++) {
        int row = (mtb + mt) * 16 + (lane >> 2);
#pragma unroll
        for (int nt = 0; nt < 4; nt++) {
            int col = (ntb + nt) * 8 + (lane & 3) * 2;
            float bb0 = bx[col] + bh[col];
            float bb1 = bx[col + 1] + bh[col + 1];
            float2 v0 = make_float2(acc[mt][nt][0] + bb0, acc[mt][nt][1] + bb1);
            float2 v1 = make_float2(acc[mt][nt][2] + bb0, acc[mt][nt][3] + bb1);
            *(float2*)(g_gx + (size_t)row * G4 + col) = v0;
            *(float2*)(g_gx + (size_t)(row + 8) * G4 + col) = v1;
        }
    }
}

// ---------------------------------------------------------------------------
// Persistent recurrence: 128 CTAs x 256 threads, 1 CTA/SM (R13/R15 layout).
// Warp w = (q = w&3, nh = w>>2); Wh A-fragments in registers.
// R16 barrier: 4 quarter counters. CTA c (producing kt = c>>1, quarter c>>5)
// release-adds to counter[c>>5] after its publish-sync. Warp q waits ONLY on
// counter[q] (target 32*t) at its GEMM head — laggard skew overlaps compute.
// Safety: the publish happens after a CTA-wide __syncthreads that follows all
// 8 warps' GEMMs (all four q waited => all 128 producers of h(t) arrived
// => every CTA finished its step t-1 reads), so no buffer slot is overwritten
// while a straggler still reads it.
// ---------------------------------------------------------------------------
#define SO_CS   (34816)                      // Gs 4*32*68*4
#define SM_TOTAL (SO_CS + 2048)              // 36864

__global__ __launch_bounds__(256, 1) void lstm_rec(
    const float* __restrict__ c0,
    float* __restrict__ out,
    float* __restrict__ hfin, float* __restrict__ cfin,
    int full)
{
    extern __shared__ __align__(16) char sm[];
    float (*Gs)[32][68] = (float (*)[32][68])sm;
    float* cs = (float*)(sm + SO_CS);

    const int cta = blockIdx.x;
    const int tid = threadIdx.x;
    const int w = tid >> 5, lane = tid & 31;
    const int q = w & 3, nh = w >> 2;
    const int r0q = lane >> 2;
    const int c0q = (lane & 3) * 2;
    int* my_arrive = &g_arrive4[(cta >> 5) * 32];
    const int* my_wait = &g_arrive4[q * 32];

    // ---- init: Wh A-fragments -> registers (once); cell state -> smem ----
    uint32_t areg[2][16][4];
    {
        const uint32_t* src = g_whp + (size_t)cta * 16384;
        const int ktb = q * 16;
#pragma unroll
        for (int mt = 0; mt < 2; mt++)
#pragma unroll
            for (int kl = 0; kl < 16; kl++) {
                *(uint4*)areg[mt][kl] =
                    *(const uint4*)(src + ((size_t)mt * 64 + ktb + kl) * 128 + lane * 4);
            }
        for (int i = tid; i < 512; i += 256) {
            int b = i >> 3, ul = i & 7;
            cs[i] = c0[(size_t)b * HH + cta * 8 + ul];
        }
    }
    __syncthreads();

    const int kt0 = q * 16;
    for (int t = 0; t < TT; t++) {
        // ---- per-warp quarter wait: producers of my K-quarter done? ----
        if (t > 0) {
            if (lane == 0) {
                const int target = 32 * t;
                while (bar_acquire_ld(my_wait) < target) __nanosleep(32);
            }
            __syncwarp();
        }

        // ---- prefetch gate pre-activations (hidden under GEMM) ----
        float gpre[2][4];
#pragma unroll
        for (int pp = 0; pp < 2; pp++) {
            const int p = tid + pp * 256;
            const int b = p >> 3, ul = p & 7;
            const float* gxr = g_gx + ((size_t)t * BB + b) * G4 + cta * 8 + ul;
#pragma unroll
            for (int g = 0; g < 4; g++) gpre[pp][g] = __ldcg(gxr + g * HH);
        }

        // ---- rec GEMM: (q, nh) warp tile, A in registers ----
        float acc[2][4][4];
#pragma unroll
        for (int i = 0; i < 2; i++)
#pragma unroll
            for (int j = 0; j < 4; j++)
#pragma unroll
                for (int r = 0; r < 4; r++) acc[i][j][r] = 0.f;

        const uint32_t* Bf = &g_hfrag[t & 1][0];
#pragma unroll
        for (int kl = 0; kl < 16; kl++) {
            const int kt = kt0 + kl;
            uint2 bf[4];
#pragma unroll
            for (int ntl = 0; ntl < 4; ntl++) {
                uint32_t off = (uint32_t)(kt * 8 + nh * 4 + ntl) * 64 + lane * 2;
                bf[ntl] = __ldcg((const uint2*)(Bf + off));
            }
#pragma unroll
            for (int ntl = 0; ntl < 4; ntl++) {
                mma16816(acc[0][ntl], areg[0][kl], (const uint32_t*)&bf[ntl]);
                mma16816(acc[1][ntl], areg[1][kl], (const uint32_t*)&bf[ntl]);
            }
        }

        // ---- scatter partials: Gs[q][row32][b] ----
#pragma unroll
        for (int mt = 0; mt < 2; mt++) {
            const int rbase = mt * 16 + r0q;
#pragma unroll
            for (int ntl = 0; ntl < 4; ntl++) {
                int col = (nh * 4 + ntl) * 8 + c0q;
                Gs[q][rbase][col]     = acc[mt][ntl][0];
                Gs[q][rbase][col + 1] = acc[mt][ntl][1];
                Gs[q][rbase + 8][col]     = acc[mt][ntl][2];
                Gs[q][rbase + 8][col + 1] = acc[mt][ntl][3];
            }
        }
        __syncthreads();

        // ---- cell update: 2 cells per thread ----
        float* outt = out + (size_t)t * BB * HH;
        const int nb = (t + 1) & 1;
        float hsave[2], csave[2];
#pragma unroll
        for (int pp = 0; pp < 2; pp++) {
            const int p = tid + pp * 256;
            const int b = p >> 3, ul = p & 7;
            const int u = cta * 8 + ul;

            float x0 = Gs[0][ul][b] + Gs[1][ul][b] + Gs[2][ul][b] + Gs[3][ul][b] + gpre[pp][0];
            float x1 = Gs[0][8 + ul][b] + Gs[1][8 + ul][b] + Gs[2][8 + ul][b] + Gs[3][8 + ul][b] + gpre[pp][1];
            float x2 = Gs[0][16 + ul][b] + Gs[1][16 + ul][b] + Gs[2][16 + ul][b] + Gs[3][16 + ul][b] + gpre[pp][2];
            float x3 = Gs[0][24 + ul][b] + Gs[1][24 + ul][b] + Gs[2][24 + ul][b] + Gs[3][24 + ul][b] + gpre[pp][3];

            float ig = fast_sigmoid(x0);
            float fg = fast_sigmoid(x1);
            float og = fast_sigmoid(x2);
            float ng = fast_tanh(x3);

            float cprev = cs[p];
            float cnew = fg * cprev + ig * ng;
            float hnew = og * fast_tanh(cnew);
            cs[p] = cnew;
            hsave[pp] = hnew;
            csave[pp] = cnew;

            // publish next-step B fragment (fp16)
            int kt = u >> 4, kk = u & 15, nt = b >> 3;
            int lt = ((b & 7) << 2) | ((kk >> 1) & 3);
            int rg = kk >> 3, hf = kk & 1;
            size_t wi = ((size_t)(kt * 8 + nt) * 32 + lt) * 2 + rg;
            ((__half*)&g_hfrag[nb][wi])[hf] = __float2half_rn(hnew);

            if (t == TT - 1 && full) {
                hfin[(size_t)b * HH + u] = hnew;
                cfin[(size_t)b * HH + u] = cnew;
            }
        }

        // ---- arrive on my quarter counter (publishes visible) ----
        __syncthreads();
        if (tid == 0) bar_release_add(my_arrive);

        // shadow: output stores (not consumed this pass)
#pragma unroll
        for (int pp = 0; pp < 2; pp++) {
            const int p = tid + pp * 256;
            const int b = p >> 3, ul = p & 7;
            outt[(size_t)b * HH + cta * 8 + ul] = hsave[pp];
        }
    }
}

// ---------------------------------------------------------------------------
extern "C" void kernel_launch(void* const* d_in, const int* in_sizes, int n_in,
                              void* d_out, int out_size)
{
    const float* input_ = (const float*)d_in[0];
    const float* h0     = (const float*)d_in[1];
    const float* c0     = (const float*)d_in[2];
    const float* Wx     = (const float*)d_in[3];
    const float* Wh     = (const float*)d_in[4];
    const float* bx     = (const float*)d_in[5];
    const float* bh     = (const float*)d_in[6];
    float* out = (float*)d_out;
    (void)in_sizes; (void)n_in;

    cudaFuncSetAttribute(lstm_rec, cudaFuncAttributeMaxDynamicSharedMemorySize, SM_TOTAL);

    reset_bar<<<1, 32>>>();
    pack_whp<<<(G4 * HH) / 256, 256>>>(Wh);
    pack_wx<<<(G4 * HH) / 256, 256>>>(Wx);
    pack_x<<<(int)(((size_t)TT * BB * HH) / 256), 256>>>(input_);
    pack_h0<<<(BB * HH) / 256, 256>>>(h0);

    dim3 ggrid(G4 / 128, (TT * BB) / 128);
    gx_mma_kernel<<<ggrid, 256>>>(bx, bh);

    long long need = (long long)TT * BB * HH + 2LL * BB * HH;
    int full = (out_size >= need) ? 1 : 0;
    float* hfin = out + (size_t)TT * BB * HH;
    float* cfin = hfin + (size_t)BB * HH;

    lstm_rec<<<NCTA, 256, SM_TOTAL>>>(c0, out, hfin, cfin, full);
}